// round 9
// baseline (speedup 1.0000x reference)
#include <cuda_runtime.h>
#include <cuda_bf16.h>
#include <cstdint>
#include <cstddef>

#define NN   8192
#define DF   784
#define DFP  800     // padded K (25 * 32)
#define DEMB 256
#define TK   11
#define TK2  24      // coarse candidate count
#define NCB  64      // column blocks per row (NN / 128)
#define SCAP 192     // per-row survivor capacity

// ---------------- scratch (static device globals; no allocs) ----------------
__device__ float g_sq[NN];
__device__ __align__(16) __nv_bfloat16 g_Xb[(size_t)NN * DFP];
__device__ float g_bmin[(size_t)NN * NCB];
__device__ float g_T[NN];
__device__ int   g_scnt[NN];
__device__ unsigned long long g_sbuf[(size_t)NN * SCAP];
__device__ int   g_idx24[NN * TK2];
__device__ int   g_idx[NN * TK];
__device__ int   g_cnt[NN];
__device__ float g_dv[NN];
__device__ float g_G[(size_t)NN * DF];

__device__ __forceinline__ unsigned smem_u32(const void* p) {
    return (unsigned)__cvta_generic_to_shared(p);
}

// ---------------- 0. convert X -> bf16 (zero-pad K to 800) ----------------
__global__ void conv_kernel(const float* __restrict__ X) {
    int row = blockIdx.x;
    for (int c = threadIdx.x; c < DFP; c += 256) {
        g_Xb[(size_t)row * DFP + c] =
            (c < DF) ? __float2bfloat16_rn(X[(size_t)row * DF + c]) : __float2bfloat16_rn(0.f);
    }
}

// ---------------- 1. row squared norms (correctly rounded) ----------------
__global__ void sq_kernel(const float* __restrict__ X) {
    int row  = blockIdx.x * 8 + (threadIdx.x >> 5);
    int lane = threadIdx.x & 31;
    const float* xr = X + (size_t)row * DF;
    float s = 0.f, c = 0.f;
    for (int k = lane; k < DF; k += 32) {
        float v = xr[k];
        float p = __fmul_rn(v, v);
        float y = __fsub_rn(p, c);
        float t = __fadd_rn(s, y);
        c = __fsub_rn(__fsub_rn(t, s), y);
        s = t;
    }
    double d = (double)s + (double)c;
    #pragma unroll
    for (int o = 16; o; o >>= 1) d += __shfl_xor_sync(0xffffffffu, d, o);
    if (lane == 0) g_sq[row] = (float)d;
}

// ---------------- shared MMA mainloop: 128x128 tile of Xb @ Xb^T ----------------
#define SROW 40

__device__ __forceinline__ void mma_tile(int bi, int bj, int tid,
                                         __nv_bfloat16* As, __nv_bfloat16* Bs,
                                         float (&acc)[4][4][4]) {
    int warp = tid >> 5, lane = tid & 31;
    int wm = (warp >> 2) * 64;
    int wn = (warp & 3) * 32;

    #pragma unroll
    for (int m = 0; m < 4; m++)
        #pragma unroll
        for (int n = 0; n < 4; n++)
            #pragma unroll
            for (int r = 0; r < 4; r++) acc[m][n][r] = 0.f;

    for (int kt = 0; kt < DFP / 32; kt++) {
        #pragma unroll
        for (int l = 0; l < 2; l++) {
            int q = tid + l * 256;
            int row = q >> 2, ch = q & 3;
            const int4* sa = (const int4*)(g_Xb + (size_t)(bi + row) * DFP + kt * 32 + ch * 8);
            *(int4*)(As + row * SROW + ch * 8) = *sa;
            const int4* sb = (const int4*)(g_Xb + (size_t)(bj + row) * DFP + kt * 32 + ch * 8);
            *(int4*)(Bs + row * SROW + ch * 8) = *sb;
        }
        __syncthreads();

        #pragma unroll
        for (int ks = 0; ks < 2; ks++) {
            int k0 = ks * 16;
            uint32_t a[4][4];
            #pragma unroll
            for (int mt = 0; mt < 4; mt++) {
                unsigned ad = smem_u32(As + (wm + mt * 16 + (lane & 15)) * SROW
                                          + k0 + ((lane >> 4) << 3));
                asm volatile("ldmatrix.sync.aligned.m8n8.x4.shared.b16 {%0,%1,%2,%3}, [%4];"
                             : "=r"(a[mt][0]), "=r"(a[mt][1]), "=r"(a[mt][2]), "=r"(a[mt][3])
                             : "r"(ad));
            }
            uint32_t b[4][2];
            #pragma unroll
            for (int bt = 0; bt < 2; bt++) {
                int nloc = wn + bt * 16 + ((lane >> 4) << 3) + (lane & 7);
                unsigned ad = smem_u32(Bs + nloc * SROW + k0 + (((lane >> 3) & 1) << 3));
                uint32_t r0, r1, r2, r3;
                asm volatile("ldmatrix.sync.aligned.m8n8.x4.shared.b16 {%0,%1,%2,%3}, [%4];"
                             : "=r"(r0), "=r"(r1), "=r"(r2), "=r"(r3) : "r"(ad));
                b[2 * bt][0] = r0; b[2 * bt][1] = r1;
                b[2 * bt + 1][0] = r2; b[2 * bt + 1][1] = r3;
            }
            #pragma unroll
            for (int mt = 0; mt < 4; mt++)
                #pragma unroll
                for (int nt = 0; nt < 4; nt++) {
                    asm volatile(
                        "mma.sync.aligned.m16n8k16.row.col.f32.bf16.bf16.f32 "
                        "{%0,%1,%2,%3}, {%4,%5,%6,%7}, {%8,%9}, {%0,%1,%2,%3};"
                        : "+f"(acc[mt][nt][0]), "+f"(acc[mt][nt][1]),
                          "+f"(acc[mt][nt][2]), "+f"(acc[mt][nt][3])
                        : "r"(a[mt][0]), "r"(a[mt][1]), "r"(a[mt][2]), "r"(a[mt][3]),
                          "r"(b[nt][0]), "r"(b[nt][1]));
                }
        }
        __syncthreads();
    }
}

// transform acc -> distances in place
__device__ __forceinline__ void acc_to_dist(int bi, int bj, int tid,
                                            float (&acc)[4][4][4]) {
    int warp = tid >> 5, lane = tid & 31;
    int wm = (warp >> 2) * 64, wn = (warp & 3) * 32;
    int r_in = lane >> 2, cb = (lane & 3) * 2;
    #pragma unroll
    for (int mt = 0; mt < 4; mt++)
        #pragma unroll
        for (int half = 0; half < 2; half++) {
            float sqi = g_sq[bi + wm + mt * 16 + r_in + half * 8];
            #pragma unroll
            for (int nt = 0; nt < 4; nt++) {
                int gj = bj + wn + nt * 8 + cb;
                acc[mt][nt][half * 2 + 0] =
                    fabsf(sqi + g_sq[gj]     - 2.f * acc[mt][nt][half * 2 + 0]);
                acc[mt][nt][half * 2 + 1] =
                    fabsf(sqi + g_sq[gj + 1] - 2.f * acc[mt][nt][half * 2 + 1]);
            }
        }
}

// ---------------- 2. pass 1: block-mins (row + col) and H zeros; no D store ----------------
__global__ __launch_bounds__(256) void dist_p1(float* __restrict__ H) {
    if (blockIdx.y > blockIdx.x) return;             // upper triangle only
    __shared__ __nv_bfloat16 As[128 * SROW];
    __shared__ __nv_bfloat16 Bs[128 * SROW];
    __shared__ float swm[128][4];
    __shared__ float scm[128][2];

    int tid = threadIdx.x;
    int bi = blockIdx.y * 128, bj = blockIdx.x * 128;
    int warp = tid >> 5, lane = tid & 31;
    int wm = (warp >> 2) * 64, wn = (warp & 3) * 32;
    int r_in = lane >> 2, cb = (lane & 3) * 2;

    float acc[4][4][4];
    mma_tile(bi, bj, tid, As, Bs, acc);
    acc_to_dist(bi, bj, tid, acc);

    // row-min
    #pragma unroll
    for (int mt = 0; mt < 4; mt++)
        #pragma unroll
        for (int half = 0; half < 2; half++) {
            float rmin = 3.4e38f;
            #pragma unroll
            for (int nt = 0; nt < 4; nt++)
                rmin = fminf(rmin, fminf(acc[mt][nt][half * 2], acc[mt][nt][half * 2 + 1]));
            rmin = fminf(rmin, __shfl_xor_sync(0xffffffffu, rmin, 1));
            rmin = fminf(rmin, __shfl_xor_sync(0xffffffffu, rmin, 2));
            if ((lane & 3) == 0)
                swm[wm + mt * 16 + r_in + half * 8][warp & 3] = rmin;
        }

    // col-min
    #pragma unroll
    for (int nt = 0; nt < 4; nt++) {
        float v0 = 3.4e38f, v1 = 3.4e38f;
        #pragma unroll
        for (int mt = 0; mt < 4; mt++) {
            v0 = fminf(v0, fminf(acc[mt][nt][0], acc[mt][nt][2]));
            v1 = fminf(v1, fminf(acc[mt][nt][1], acc[mt][nt][3]));
        }
        #pragma unroll
        for (int o = 4; o <= 16; o <<= 1) {
            v0 = fminf(v0, __shfl_xor_sync(0xffffffffu, v0, o));
            v1 = fminf(v1, __shfl_xor_sync(0xffffffffu, v1, o));
        }
        if (r_in == 0) {
            scm[wn + nt * 8 + cb + 0][wm >> 6] = v0;
            scm[wn + nt * 8 + cb + 1][wm >> 6] = v1;
        }
    }
    __syncthreads();

    if (tid < 128) {
        float m = fminf(fminf(swm[tid][0], swm[tid][1]),
                        fminf(swm[tid][2], swm[tid][3]));
        g_bmin[(size_t)(bi + tid) * NCB + blockIdx.x] = m;
        if (bi != bj) {
            float c = fminf(scm[tid][0], scm[tid][1]);
            g_bmin[(size_t)(bj + tid) * NCB + blockIdx.y] = c;
        }
    }

    // fused H zeros (both mirror rectangles)
    float4 z4 = make_float4(0.f, 0.f, 0.f, 0.f);
    float4* Hq = (float4*)H;
    #pragma unroll
    for (int q = 0; q < 16; q++) {
        int lin = q * 256 + tid;
        int r = lin >> 5, c = lin & 31;
        Hq[(size_t)(bi + r) * (NN / 4) + (bj >> 2) + c] = z4;
    }
    if (bi != bj) {
        #pragma unroll
        for (int q = 0; q < 16; q++) {
            int lin = q * 256 + tid;
            int r = lin >> 5, c = lin & 31;
            Hq[(size_t)(bj + r) * (NN / 4) + (bi >> 2) + c] = z4;
        }
    }
}

// ---------------- 3. threshold: T[row] = 24th smallest of 64 block-mins ----------------
__global__ __launch_bounds__(256) void thresh_kernel() {
    int warp = threadIdx.x >> 5, lane = threadIdx.x & 31;
    int row = blockIdx.x * 8 + warp;
    __shared__ float sb[8][64];
    sb[warp][lane]      = g_bmin[(size_t)row * NCB + lane];
    sb[warp][lane + 32] = g_bmin[(size_t)row * NCB + lane + 32];
    __syncwarp();
    if (lane == 0) {
        float best[TK2];
        #pragma unroll
        for (int k = 0; k < TK2; k++) best[k] = 3.4e38f;
        for (int i = 0; i < NCB; i++) {
            float x = sb[warp][i];
            if (x < best[TK2 - 1]) {
                int k = TK2 - 1;
                while (k > 0 && best[k - 1] > x) { best[k] = best[k - 1]; k--; }
                best[k] = x;
            }
        }
        g_T[row] = best[TK2 - 1];
    }
}

__global__ void zero_scnt() {
    int t = blockIdx.x * 256 + threadIdx.x;
    if (t < NN) g_scnt[t] = 0;
}

// ---------------- 4. pass 2: recompute, filter survivors both directions ----------------
__global__ __launch_bounds__(256) void dist_p2() {
    if (blockIdx.y > blockIdx.x) return;
    __shared__ __nv_bfloat16 As[128 * SROW];
    __shared__ __nv_bfloat16 Bs[128 * SROW];

    int tid = threadIdx.x;
    int bi = blockIdx.y * 128, bj = blockIdx.x * 128;
    int warp = tid >> 5, lane = tid & 31;
    int wm = (warp >> 2) * 64, wn = (warp & 3) * 32;
    int r_in = lane >> 2, cb = (lane & 3) * 2;

    float acc[4][4][4];
    mma_tile(bi, bj, tid, As, Bs, acc);
    acc_to_dist(bi, bj, tid, acc);

    float Ti[8], Tj[8];
    #pragma unroll
    for (int mt = 0; mt < 4; mt++)
        #pragma unroll
        for (int half = 0; half < 2; half++)
            Ti[mt * 2 + half] = g_T[bi + wm + mt * 16 + r_in + half * 8];
    #pragma unroll
    for (int nt = 0; nt < 4; nt++) {
        Tj[nt * 2 + 0] = g_T[bj + wn + nt * 8 + cb + 0];
        Tj[nt * 2 + 1] = g_T[bj + wn + nt * 8 + cb + 1];
    }

    bool offdiag = (bi != bj);
    #pragma unroll
    for (int mt = 0; mt < 4; mt++)
        #pragma unroll
        for (int nt = 0; nt < 4; nt++)
            #pragma unroll
            for (int r = 0; r < 4; r++) {
                int half = r >> 1, par = r & 1;
                float d = acc[mt][nt][r];
                int gi = bi + wm + mt * 16 + r_in + half * 8;
                int gj = bj + wn + nt * 8 + cb + par;
                if (d <= Ti[mt * 2 + half]) {
                    int p = atomicAdd(&g_scnt[gi], 1);
                    if (p < SCAP)
                        g_sbuf[(size_t)gi * SCAP + p] =
                            ((unsigned long long)__float_as_uint(d) << 32) | (unsigned)gj;
                }
                if (offdiag && d <= Tj[nt * 2 + par]) {
                    int p = atomicAdd(&g_scnt[gj], 1);
                    if (p < SCAP)
                        g_sbuf[(size_t)gj * SCAP + p] =
                            ((unsigned long long)__float_as_uint(d) << 32) | (unsigned)gi;
                }
            }
}

// ---------------- 5. select top-24 from survivors (exact fallback if overflow) ----------------
__global__ __launch_bounds__(32) void select_kernel(const float* __restrict__ X) {
    int row = blockIdx.x;
    int lane = threadIdx.x;
    int n = g_scnt[row];

    if (n <= SCAP) {
        if (lane == 0) {
            unsigned long long best[TK2];
            #pragma unroll
            for (int k = 0; k < TK2; k++) best[k] = ~0ull;
            for (int i = 0; i < n; i++) {
                unsigned long long x = g_sbuf[(size_t)row * SCAP + i];
                if (x < best[TK2 - 1]) {
                    int k = TK2 - 1;
                    while (k > 0 && best[k - 1] > x) { best[k] = best[k - 1]; k--; }
                    best[k] = x;
                }
            }
            #pragma unroll
            for (int k = 0; k < TK2; k++) g_idx24[row * TK2 + k] = (int)(unsigned)best[k];
        }
        return;
    }

    // fallback (statistically unreachable): exact fp32 coarse scan of the row
    unsigned long long loc[TK2];
    #pragma unroll
    for (int k = 0; k < TK2; k++) loc[k] = ~0ull;
    float sqi = g_sq[row];
    const float* xi = X + (size_t)row * DF;
    for (int j = lane; j < NN; j += 32) {
        const float* xj = X + (size_t)j * DF;
        float dot = 0.f;
        for (int k = 0; k < DF; k++) dot = fmaf(xi[k], xj[k], dot);
        float d = fabsf(sqi + g_sq[j] - 2.f * dot);
        unsigned long long x =
            ((unsigned long long)__float_as_uint(d) << 32) | (unsigned)j;
        if (x < loc[TK2 - 1]) {
            int k = TK2 - 1;
            while (k > 0 && loc[k - 1] > x) { loc[k] = loc[k - 1]; k--; }
            loc[k] = x;
        }
    }
    __shared__ unsigned long long sh[32 * TK2];
    #pragma unroll
    for (int k = 0; k < TK2; k++) sh[lane * TK2 + k] = loc[k];
    __syncwarp();
    int p = 0;
    for (int out = 0; out < TK2; out++) {
        unsigned long long m = (p < TK2) ? sh[lane * TK2 + p] : ~0ull;
        #pragma unroll
        for (int o = 16; o; o >>= 1) {
            unsigned long long other = __shfl_xor_sync(0xffffffffu, m, o);
            if (other < m) m = other;
        }
        if (p < TK2 && sh[lane * TK2 + p] == m) p++;
        if (lane == 0) g_idx24[row * TK2 + out] = (int)(unsigned)m;
        __syncwarp();
    }
}

// ---------------- 6. refine: exact dists with ref's rounding chain, pick top-11 ----------------
__global__ __launch_bounds__(128) void refine_kernel(const float* __restrict__ X) {
    int row = blockIdx.x;
    int wid = threadIdx.x >> 5, lane = threadIdx.x & 31;
    __shared__ unsigned long long keys[TK2];
    __shared__ int cand[TK2];
    if (threadIdx.x < TK2) cand[threadIdx.x] = g_idx24[row * TK2 + threadIdx.x];
    __syncthreads();

    float sqi = g_sq[row];
    const float* xi = X + (size_t)row * DF;

    for (int k4 = wid; k4 < TK2; k4 += 4) {
        int j = cand[k4];
        const float* xj = X + (size_t)j * DF;
        float s = 0.f, c = 0.f;
        for (int k = lane; k < DF; k += 32) {
            float p = __fmul_rn(xi[k], xj[k]);
            float y = __fsub_rn(p, c);
            float t = __fadd_rn(s, y);
            c = __fsub_rn(__fsub_rn(t, s), y);
            s = t;
        }
        double d = (double)s + (double)c;
        #pragma unroll
        for (int o = 16; o; o >>= 1) d += __shfl_xor_sync(0xffffffffu, d, o);
        if (lane == 0) {
            float dotf = (float)d;
            float t1 = __fadd_rn(sqi, g_sq[j]);
            float t3 = fabsf(__fsub_rn(t1, __fmul_rn(2.0f, dotf)));
            keys[k4] = ((unsigned long long)__float_as_uint(t3) << 32) | (unsigned)j;
        }
    }
    __syncthreads();

    if (threadIdx.x == 0) {
        unsigned long long a[TK2];
        #pragma unroll
        for (int i = 0; i < TK2; i++) a[i] = keys[i];
        #pragma unroll
        for (int i = 1; i < TK2; i++) {
            unsigned long long v = a[i];
            int k = i - 1;
            while (k >= 0 && a[k] > v) { a[k + 1] = a[k]; k--; }
            a[k + 1] = v;
        }
        #pragma unroll
        for (int k = 0; k < TK; k++) g_idx[row * TK + k] = (int)(unsigned)a[k];
    }
}

// ---------------- 7. degrees / zero / scatter / gather / gemm / E ----------------
__global__ void zero_cnt() {
    int t = blockIdx.x * 256 + threadIdx.x;
    if (t < NN) g_cnt[t] = 0;
}
__global__ void count_kernel() {
    int t = blockIdx.x * 256 + threadIdx.x;
    if (t < NN * TK) atomicAdd(&g_cnt[g_idx[t]], 1);
}
__global__ void dv_kernel() {
    int t = blockIdx.x * 256 + threadIdx.x;
    if (t < NN) g_dv[t] = 1.0f / sqrtf((float)g_cnt[t]);
}

__global__ void zero_kernel(float4* __restrict__ p, size_t n4) {
    size_t t = (size_t)blockIdx.x * blockDim.x + threadIdx.x;
    size_t stride = (size_t)gridDim.x * blockDim.x;
    float4 z = make_float4(0.f, 0.f, 0.f, 0.f);
    for (size_t i = t; i < n4; i += stride) p[i] = z;
}

__global__ void scatterH(float* __restrict__ H) {
    int t = blockIdx.x * 256 + threadIdx.x;
    if (t < NN * TK) {
        int i = t / TK;
        int r = g_idx[t];
        H[(size_t)r * NN + i] = 1.0f;
    }
}

__global__ __launch_bounds__(256) void gather_kernel(const float* __restrict__ X) {
    int i = blockIdx.x;
    __shared__ int   sidx[TK];
    __shared__ float sdv[TK];
    if (threadIdx.x < TK) {
        int r = g_idx[i * TK + threadIdx.x];
        sidx[threadIdx.x] = r;
        sdv[threadIdx.x]  = g_dv[r];
    }
    __syncthreads();
    for (int c = threadIdx.x; c < DF; c += 256) {
        float s = 0.f;
        #pragma unroll
        for (int k = 0; k < TK; k++)
            s = fmaf(sdv[k], X[(size_t)sidx[k] * DF + c], s);
        g_G[(size_t)i * DF + c] = s;
    }
}

#define BK 16
#define SPAD 4
__global__ __launch_bounds__(256) void out_gemm(const float* __restrict__ theta,
                                                float* __restrict__ Xout) {
    __shared__ float As[BK][64 + SPAD];
    __shared__ float Bs[BK][64 + SPAD];
    int tid = threadIdx.x;
    int tx = tid & 15, ty = tid >> 4;
    int bi = blockIdx.y * 64, bj = blockIdx.x * 64;

    float acc[4][4];
    #pragma unroll
    for (int m = 0; m < 4; m++)
        #pragma unroll
        for (int n = 0; n < 4; n++) acc[m][n] = 0.f;

    for (int k0 = 0; k0 < DF; k0 += BK) {
        {
            int row = tid >> 2, c4 = (tid & 3) * 4;
            float4 v = *reinterpret_cast<const float4*>(g_G + (size_t)(bi + row) * DF + k0 + c4);
            As[c4 + 0][row] = v.x; As[c4 + 1][row] = v.y;
            As[c4 + 2][row] = v.z; As[c4 + 3][row] = v.w;
            int kr = tid >> 4, n4 = (tid & 15) * 4;
            float4 w = *reinterpret_cast<const float4*>(theta + (size_t)(k0 + kr) * DEMB + bj + n4);
            Bs[kr][n4 + 0] = w.x; Bs[kr][n4 + 1] = w.y;
            Bs[kr][n4 + 2] = w.z; Bs[kr][n4 + 3] = w.w;
        }
        __syncthreads();
        #pragma unroll
        for (int kk = 0; kk < BK; kk++) {
            float a[4], b[4];
            #pragma unroll
            for (int m = 0; m < 4; m++) a[m] = As[kk][ty * 4 + m];
            #pragma unroll
            for (int n = 0; n < 4; n++) b[n] = Bs[kk][tx * 4 + n];
            #pragma unroll
            for (int m = 0; m < 4; m++)
                #pragma unroll
                for (int n = 0; n < 4; n++) acc[m][n] = fmaf(a[m], b[n], acc[m][n]);
        }
        __syncthreads();
    }
    const float de = 0.30151134457776363f;  // 11^-0.5
    #pragma unroll
    for (int m = 0; m < 4; m++) {
        int i = bi + ty * 4 + m;
        float4 o;
        o.x = de * acc[m][0]; o.y = de * acc[m][1];
        o.z = de * acc[m][2]; o.w = de * acc[m][3];
        *reinterpret_cast<float4*>(Xout + (size_t)i * DEMB + bj + tx * 4) = o;
    }
}

__global__ void scatterE(const float* __restrict__ Xout, float* __restrict__ E) {
    int j = blockIdx.x;
    int c = threadIdx.x;
    float v = Xout[(size_t)j * DEMB + c];
    #pragma unroll
    for (int k = 0; k < TK; k++) {
        int r = __ldg(&g_idx[j * TK + k]);
        atomicAdd(E + (size_t)r * DEMB + c, v);
    }
}
__global__ void scaleE(float* __restrict__ E) {
    int t = blockIdx.x * 256 + threadIdx.x;
    const float de = 0.30151134457776363f;
    int i = t >> 8;
    E[t] *= g_dv[i] * de;
}

// ---------------- launch ----------------
extern "C" void kernel_launch(void* const* d_in, const int* in_sizes, int n_in,
                              void* d_out, int out_size) {
    const float* X     = (const float*)d_in[0];
    const float* theta = (const float*)d_in[1];
    float* out  = (float*)d_out;
    float* Xout = out;                                // [8192, 256]
    float* E    = out + (size_t)NN * DEMB;            // [8192, 256]
    float* H    = out + 2 * (size_t)NN * DEMB;        // [8192, 8192]

    conv_kernel<<<NN, 256>>>(X);
    sq_kernel<<<NN / 8, 256>>>(X);
    dist_p1<<<dim3(NN / 128, NN / 128), 256>>>(H);    // upper-tri MMA: blockmins + H zeros
    thresh_kernel<<<NN / 8, 256>>>();
    zero_scnt<<<NN / 256, 256>>>();
    dist_p2<<<dim3(NN / 128, NN / 128), 256>>>();     // upper-tri MMA: survivor filter
    select_kernel<<<NN, 32>>>(X);
    refine_kernel<<<NN, 128>>>(X);                    // exact-emulated top-11
    zero_cnt<<<NN / 256, 256>>>();
    count_kernel<<<(NN * TK + 255) / 256, 256>>>();
    dv_kernel<<<NN / 256, 256>>>();
    scatterH<<<(NN * TK + 255) / 256, 256>>>(H);
    gather_kernel<<<NN, 256>>>(X);
    out_gemm<<<dim3(DEMB / 64, NN / 64), 256>>>(theta, Xout);
    zero_kernel<<<256, 256>>>((float4*)E, (size_t)NN * DEMB / 4);
    scatterE<<<NN, 256>>>(Xout, E);
    scaleE<<<NN * DEMB / 256, 256>>>(E);
}